// round 13
// baseline (speedup 1.0000x reference)
#include <cuda_runtime.h>
#include <cstdint>

#define WPB 4                 // warps per block
#define SERIAL 4              // serial graph-quads per warp (16 graphs/warp total)
#define GSTRIDE 836           // floats per graph region; == 4 mod 32 (bank-disjoint quads)
#define NREG (WPB * 4)        // 16 concurrent graph regions per block
#define SMEM_FLOATS (NREG * GSTRIDE + 16)
#define SMEM_BYTES (SMEM_FLOATS * 4)

// region-internal offsets (floats)
#define OFF_NA 512            // 16x16 nA (rows, chunk-rotated)
#define OFF_DS 768
#define OFF_XS 784
#define OFF_YS 800
#define OFF_TS 816
#define ASTR 20               // raw-z staging row stride (floats); strip = 16x20, aliases HT

__device__ float g_Wt[2048];  // [layer][k][h] transposed weights

__global__ void wt_kernel(const float* __restrict__ w2, const float* __restrict__ w3) {
    for (int idx = threadIdx.x; idx < 2048; idx += blockDim.x) {
        int m = idx >> 10, rem = idx & 1023, k = rem >> 5, h = rem & 31;
        g_Wt[idx] = (m ? w3 : w2)[h * 32 + k];
    }
}

// ---------- packed f32x2 helpers (Blackwell fma.rn.f32x2, PTX-only) ----------
__device__ __forceinline__ unsigned long long fma2(unsigned long long a,
                                                   unsigned long long b,
                                                   unsigned long long c) {
    unsigned long long d;
    asm("fma.rn.f32x2 %0, %1, %2, %3;" : "=l"(d) : "l"(a), "l"(b), "l"(c));
    return d;
}
__device__ __forceinline__ unsigned long long pack2(float lo, float hi) {
    unsigned long long r;
    asm("mov.b64 %0, {%1, %2};" : "=l"(r) : "f"(lo), "f"(hi));
    return r;
}
__device__ __forceinline__ unsigned long long dup2(float v) {
    unsigned long long r;
    asm("mov.b64 %0, {%1, %1};" : "=l"(r) : "f"(v));
    return r;
}
__device__ __forceinline__ float hsum2(unsigned long long v) {
    float a, b;
    asm("mov.b64 {%0, %1}, %2;" : "=f"(a), "=f"(b) : "l"(v));
    return a + b;
}
__device__ __forceinline__ void unpack2(unsigned long long v, float& a, float& b) {
    asm("mov.b64 {%0, %1}, %2;" : "=f"(a), "=f"(b) : "l"(v));
}
__device__ __forceinline__ uint32_t smem_u32(const void* p) {
    uint32_t a;
    asm("{ .reg .u64 t; cvta.to.shared.u64 t, %1; cvt.u32.u64 %0, t; }" : "=r"(a) : "l"(p));
    return a;
}
__device__ __forceinline__ void cp_async16(uint32_t dst, const void* src) {
    asm volatile("cp.async.ca.shared.global [%0], [%1], 16;" :: "r"(dst), "l"(src));
}
#define CP_COMMIT() asm volatile("cp.async.commit_group;" ::: "memory")
#define CP_WAIT0()  asm volatile("cp.async.wait_group 0;" ::: "memory")

// stage raw z rows r0,r1 of this lane's graph into the RAW strip (16B chunks)
__device__ __forceinline__ void stage_z(uint32_t raw_s, const float* zg, int r0) {
#pragma unroll
    for (int rr = 0; rr < 2; rr++) {
        const int r = r0 + rr;
#pragma unroll
        for (int q = 0; q < 4; q++)
            cp_async16(raw_s + (uint32_t)(r * (ASTR * 4) + q * 16),
                       zg + r * 16 + 4 * q);
    }
}

// G[j][h_c] += sum_k H[j][k] * W[h_c][k]  (j-pair packed; HT k-major, slot-rotated)
__device__ __forceinline__ void hw_layer_q(const float* __restrict__ HT,
                                           const float* __restrict__ wt,     // g_Wt + m*1024
                                           const float* __restrict__ bias,   // layer bias
                                           int j0,
                                           unsigned long long Gp[4][8]) {
    float4 bv = *(const float4*)(bias + 4 * j0);
    unsigned long long b0 = dup2(bv.x), b1 = dup2(bv.y), b2 = dup2(bv.z), b3 = dup2(bv.w);
#pragma unroll
    for (int jp = 0; jp < 8; jp++) {
        Gp[0][jp] = b0; Gp[1][jp] = b1; Gp[2][jp] = b2; Gp[3][jp] = b3;
    }
#pragma unroll
    for (int k = 0; k < 32; k++) {
        const int rot = k >> 2;                       // slot rotation used by row-k's writer
        const ulonglong2* row = (const ulonglong2*)(HT + k * 16);
        ulonglong2 c0 = row[0], c1 = row[1], c2 = row[2], c3 = row[3];
        unsigned long long u[8] = {c0.x, c0.y, c1.x, c1.y, c2.x, c2.y, c3.x, c3.y};
        float4 wv = *(const float4*)(wt + k * 32 + 4 * j0);
        unsigned long long w0 = dup2(wv.x), w1 = dup2(wv.y), w2 = dup2(wv.z), w3 = dup2(wv.w);
#pragma unroll
        for (int jp = 0; jp < 8; jp++) {
            unsigned long long hv = u[(jp + rot) & 7];
            Gp[0][jp] = fma2(hv, w0, Gp[0][jp]);
            Gp[1][jp] = fma2(hv, w1, Gp[1][jp]);
            Gp[2][jp] = fma2(hv, w2, Gp[2][jp]);
            Gp[3][jp] = fma2(hv, w3, Gp[3][jp]);
        }
    }
}

// H[i][h_c] = relu(nA_row_i . G[.][h_c]); STORE -> HT (rotated), else pool into e[]
template <bool STORE>
__device__ __forceinline__ void propagate_q(const float* __restrict__ NAp,
                                            float* __restrict__ HT,
                                            const unsigned long long Gp[4][8],
                                            int j0, float* e) {
#pragma unroll
    for (int t = 0; t < 8; t++) {
        float h[2][4];
#pragma unroll
        for (int ii = 0; ii < 2; ii++) {
            const int i = 2 * t + ii;
            const int rc = (i >> 1) & 3;              // NA row chunk rotation
            unsigned long long a0 = 0ULL, a1 = 0ULL, a2 = 0ULL, a3 = 0ULL;
#pragma unroll
            for (int p = 0; p < 4; p++) {
                const int q = (p - rc) & 3;           // logical chunk at physical p
                ulonglong2 nn = *(const ulonglong2*)(NAp + i * 16 + 4 * p);
                a0 = fma2(nn.x, Gp[0][2 * q], a0); a0 = fma2(nn.y, Gp[0][2 * q + 1], a0);
                a1 = fma2(nn.x, Gp[1][2 * q], a1); a1 = fma2(nn.y, Gp[1][2 * q + 1], a1);
                a2 = fma2(nn.x, Gp[2][2 * q], a2); a2 = fma2(nn.y, Gp[2][2 * q + 1], a2);
                a3 = fma2(nn.x, Gp[3][2 * q], a3); a3 = fma2(nn.y, Gp[3][2 * q + 1], a3);
            }
            h[ii][0] = fmaxf(hsum2(a0), 0.0f);
            h[ii][1] = fmaxf(hsum2(a1), 0.0f);
            h[ii][2] = fmaxf(hsum2(a2), 0.0f);
            h[ii][3] = fmaxf(hsum2(a3), 0.0f);
        }
        if (STORE) {
            const int sp = (t + j0) & 7;              // rotated u64 slot
#pragma unroll
            for (int c = 0; c < 4; c++)
                *(unsigned long long*)(HT + (4 * j0 + c) * 16 + 2 * sp) = pack2(h[0][c], h[1][c]);
        } else {
            e[0] += h[0][0] + h[1][0];
            e[1] += h[0][1] + h[1][1];
            e[2] += h[0][2] + h[1][2];
            e[3] += h[0][3] + h[1][3];
        }
    }
}

__global__ void __launch_bounds__(WPB * 32, 4)
gcn_kernel(const float* __restrict__ z,
           const float* __restrict__ node_emb,
           const float* __restrict__ spw,
           const float* __restrict__ spb,
           const float* __restrict__ alpha,
           const float* __restrict__ w1_w, const float* __restrict__ w1_b,
           const float* __restrict__ w2_b, const float* __restrict__ w3_b,
           const float* __restrict__ fc_w, const float* __restrict__ fc_b,
           float* __restrict__ out, int batch)
{
    extern __shared__ float smem[];
    float* spwsm = smem + NREG * GSTRIDE;

    const int tid = threadIdx.x;
    const int wid  = tid >> 5;
    const int l    = tid & 31;
    const int j0   = l & 7;       // lane within graph group: nodes {2j0,2j0+1}, hidden {4j0..4j0+3}
    const int gsel = l >> 3;      // which of 4 concurrent graphs

    float* GR  = smem + (wid * 4 + gsel) * GSTRIDE;
    float* HT  = GR;              // 32x16 k-major hidden (aliases 16x20 raw-z strip)
    float* RAW = GR;              // raw z staging (prep only)
    float* NAp = GR + OFF_NA;
    const uint32_t raw_s = smem_u32(RAW);

    const int r0 = 2 * j0, r1 = 2 * j0 + 1;

    long long warpbase = ((long long)blockIdx.x * WPB + wid) * (4 * SERIAL);

    // stage quad 0's z (covered by weight staging + syncthreads)
    {
        long long g0 = warpbase + gsel;
        stage_z(raw_s, z + (g0 < batch ? g0 : 0) * 256, r0);
        CP_COMMIT();
    }

    if (tid < 16) spwsm[tid] = spw[tid];
    __syncthreads();

    // persistent lane constants
    float ne0, ne1;
    { float2 nv = *(const float2*)(node_emb + r0); ne0 = nv.x; ne1 = nv.y; }
    float spw0, spw1;
    { float2 wv = *(const float2*)(spwsm + r0); spw0 = wv.x; spw1 = wv.y; }
    const float spb0 = spb[0];
    const float blend = 1.0f / (1.0f + expf(-alpha[0]));
    const float omb = 1.0f - blend;
    float SW = 0.0f;              // sum of spw (for affine struct projection)
#pragma unroll
    for (int q = 0; q < 4; q++) {
        float4 w = *(const float4*)(spwsm + 4 * q);
        SW += w.x + w.y + w.z + w.w;
    }

#pragma unroll 1
    for (int si = 0; si < SERIAL; si++) {
        long long g = warpbase + si * 4 + gsel;
        const bool valid = (g < batch);

        // wait for this quad's staged z
        CP_WAIT0();
        __syncwarp();

        // ---- symmetrize + fused local sums (independent of the shfl tree) ----
        float s0[16], s1[16];
        float mn = 1e30f, mx = -1e30f;
        float ss0 = 0.0f, ss1 = 0.0f, sw0 = 0.0f, sw1 = 0.0f;
#pragma unroll
        for (int q = 0; q < 4; q++) {
            float4 v0 = *(const float4*)(RAW + r0 * ASTR + 4 * q);
            float4 v1 = *(const float4*)(RAW + r1 * ASTR + 4 * q);
            float4 w  = *(const float4*)(spwsm + 4 * q);
#pragma unroll
            for (int t = 0; t < 4; t++) {
                const int i = 4 * q + t;
                float2 c = *(const float2*)(RAW + i * ASTR + r0);  // z[i][r0], z[i][r1]
                float rv0 = (t == 0) ? v0.x : (t == 1) ? v0.y : (t == 2) ? v0.z : v0.w;
                float rv1 = (t == 0) ? v1.x : (t == 1) ? v1.y : (t == 2) ? v1.z : v1.w;
                float wt  = (t == 0) ? w.x  : (t == 1) ? w.y  : (t == 2) ? w.z  : w.w;
                float sv0 = 0.5f * (fabsf(rv0) + fabsf(c.x));
                float sv1 = 0.5f * (fabsf(rv1) + fabsf(c.y));
                s0[i] = sv0; s1[i] = sv1;
                mn = fminf(mn, fminf(sv0, sv1));
                mx = fmaxf(mx, fmaxf(sv0, sv1));
                ss0 += sv0; ss1 += sv1;
                sw0 += sv0 * wt; sw1 += sv1 * wt;
            }
        }
#pragma unroll
        for (int m = 4; m >= 1; m >>= 1) {
            mn = fminf(mn, __shfl_xor_sync(0xffffffffu, mn, m));
            mx = fmaxf(mx, __shfl_xor_sync(0xffffffffu, mx, m));
        }
        const float inv = 1.0f / (mx - mn + 1e-6f);

        // ---- affine row sums / struct projection (no normalize loop) ----
        // A_hat contains the identity: its diagonal contributes +1 to the row
        // sum and +spw[row] to the struct projection.
        const float rs0 = inv * (ss0 - 16.0f * mn) + 1.0f;
        const float rs1 = inv * (ss1 - 16.0f * mn) + 1.0f;
        const float sx0 = inv * (sw0 - mn * SW) + spw0;
        const float sx1 = inv * (sw1 - mn * SW) + spw1;
        const float d0 = rsqrtf(rs0 + 1e-6f);
        const float d1 = rsqrtf(rs1 + 1e-6f);
        const float x0 = blend * (sx0 + spb0) + omb * ne0;
        const float x1 = blend * (sx1 + spb0) + omb * ne1;
        *(unsigned long long*)(GR + OFF_DS + r0) = pack2(d0, d1);
        *(unsigned long long*)(GR + OFF_XS + r0) = pack2(x0, x1);
        __syncwarp();

        // ---- nA rows r0,r1 (normalization folded in); fold t = nA@1, y = nA@X ----
        float t0 = 0.0f, t1 = 0.0f, y0 = 0.0f, y1 = 0.0f;
        const float c0f = d0 * inv, c1f = d1 * inv;
        const float d00 = d0 * d0, d11 = d1 * d1;
#pragma unroll
        for (int q = 0; q < 4; q++) {
            float4 dd = *(const float4*)(GR + OFF_DS + 4 * q);
            float4 xv = *(const float4*)(GR + OFF_XS + 4 * q);
            float na0[4], na1[4];
#pragma unroll
            for (int t = 0; t < 4; t++) {
                const int i = 4 * q + t;
                float ddt = (t == 0) ? dd.x : (t == 1) ? dd.y : (t == 2) ? dd.z : dd.w;
                na0[t] = (c0f * ddt) * (s0[i] - mn);
                na1[t] = (c1f * ddt) * (s1[i] - mn);
                if (i == r0) na0[t] += d00;            // diagonal (+eye) term
                if (i == r1) na1[t] += d11;
            }
            t0 += na0[0] + na0[1] + na0[2] + na0[3];
            t1 += na1[0] + na1[1] + na1[2] + na1[3];
            y0 += na0[0] * xv.x + na0[1] * xv.y + na0[2] * xv.z + na0[3] * xv.w;
            y1 += na1[0] * xv.x + na1[1] * xv.y + na1[2] * xv.z + na1[3] * xv.w;
            const int p = (q + j0) & 3;               // rotated chunk position
            *(float4*)(NAp + r0 * 16 + 4 * p) = make_float4(na0[0], na0[1], na0[2], na0[3]);
            *(float4*)(NAp + r1 * 16 + 4 * p) = make_float4(na1[0], na1[1], na1[2], na1[3]);
        }
        *(unsigned long long*)(GR + OFF_YS + r0) = pack2(y0, y1);
        *(unsigned long long*)(GR + OFF_TS + r0) = pack2(t0, t1);
        __syncwarp();

        // ---- layer 1 (rank-2): H1[i][h] = relu(y_i*w1_h + t_i*b1_h) -> HT ----
        // (overwrites RAW strip; raw reads all completed before the prior syncwarp)
        {
            float4 w1v = *(const float4*)(w1_w + 4 * j0);
            float4 b1v = *(const float4*)(w1_b + 4 * j0);
#pragma unroll
            for (int t = 0; t < 8; t++) {
                float ya, yb, ta, tb;
                unpack2(*(const unsigned long long*)(GR + OFF_YS + 2 * t), ya, yb);
                unpack2(*(const unsigned long long*)(GR + OFF_TS + 2 * t), ta, tb);
                float ha[4], hb[4];
                ha[0] = fmaxf(ya * w1v.x + ta * b1v.x, 0.0f);
                ha[1] = fmaxf(ya * w1v.y + ta * b1v.y, 0.0f);
                ha[2] = fmaxf(ya * w1v.z + ta * b1v.z, 0.0f);
                ha[3] = fmaxf(ya * w1v.w + ta * b1v.w, 0.0f);
                hb[0] = fmaxf(yb * w1v.x + tb * b1v.x, 0.0f);
                hb[1] = fmaxf(yb * w1v.y + tb * b1v.y, 0.0f);
                hb[2] = fmaxf(yb * w1v.z + tb * b1v.z, 0.0f);
                hb[3] = fmaxf(yb * w1v.w + tb * b1v.w, 0.0f);
                const int sp = (t + j0) & 7;
#pragma unroll
                for (int c = 0; c < 4; c++)
                    *(unsigned long long*)(HT + (4 * j0 + c) * 16 + 2 * sp) = pack2(ha[c], hb[c]);
            }
        }
        __syncwarp();

        unsigned long long Gp[4][8];
        hw_layer_q(HT, g_Wt, w2_b, j0, Gp);           // G2 = H1@W2^T + b2
        __syncwarp();                                 // HT reads done before overwrite
        propagate_q<true>(NAp, HT, Gp, j0, nullptr);  // H2 -> HT
        __syncwarp();

        hw_layer_q(HT, g_Wt + 1024, w3_b, j0, Gp);    // G3 = H2@W3^T + b3
        __syncwarp();

        // HT is dead from here on: stage next quad's z into the strip (async,
        // hides DRAM latency under propagate_pool + logits)
        if (si + 1 < SERIAL) {
            long long gn = warpbase + (si + 1) * 4 + gsel;
            stage_z(raw_s, z + (gn < batch ? gn : 0) * 256, r0);
            CP_COMMIT();
        }

        float e[4] = {0.0f, 0.0f, 0.0f, 0.0f};
        propagate_q<false>(NAp, HT, Gp, j0, e);       // H3 column sums (pool)

        // ---- logits ----
        float4 f0 = *(const float4*)(fc_w + 4 * j0);
        float4 f1 = *(const float4*)(fc_w + 32 + 4 * j0);
        float p0 = e[0] * f0.x + e[1] * f0.y + e[2] * f0.z + e[3] * f0.w;
        float p1 = e[0] * f1.x + e[1] * f1.y + e[2] * f1.z + e[3] * f1.w;
#pragma unroll
        for (int m = 4; m >= 1; m >>= 1) {
            p0 += __shfl_xor_sync(0xffffffffu, p0, m);
            p1 += __shfl_xor_sync(0xffffffffu, p1, m);
        }
        if (j0 == 0 && valid) {
            float2 o;
            o.x = p0 * 0.0625f + fc_b[0];
            o.y = p1 * 0.0625f + fc_b[1];
            *(float2*)(out + g * 2) = o;
        }
        __syncwarp();
    }
}

extern "C" void kernel_launch(void* const* d_in, const int* in_sizes, int n_in,
                              void* d_out, int out_size)
{
    const float* z     = (const float*)d_in[0];
    const float* nemb  = (const float*)d_in[1];
    const float* spw   = (const float*)d_in[2];
    const float* spb   = (const float*)d_in[3];
    const float* alpha = (const float*)d_in[4];
    const float* w1w   = (const float*)d_in[5];
    const float* w1b   = (const float*)d_in[6];
    const float* w2w   = (const float*)d_in[7];
    const float* w2b   = (const float*)d_in[8];
    const float* w3w   = (const float*)d_in[9];
    const float* w3b   = (const float*)d_in[10];
    const float* fcw   = (const float*)d_in[11];
    const float* fcb   = (const float*)d_in[12];
    float* out = (float*)d_out;

    int batch = in_sizes[0] / 256;
    int graphs_per_block = WPB * 4 * SERIAL;
    int blocks = (batch + graphs_per_block - 1) / graphs_per_block;

    static bool attr_set = false;
    if (!attr_set) {
        cudaFuncSetAttribute(gcn_kernel, cudaFuncAttributeMaxDynamicSharedMemorySize,
                             SMEM_BYTES);
        attr_set = true;
    }

    wt_kernel<<<1, 256>>>(w2w, w3w);
    gcn_kernel<<<blocks, WPB * 32, SMEM_BYTES>>>(
        z, nemb, spw, spb, alpha, w1w, w1b, w2b, w3b, fcw, fcb, out, batch);
}

// round 14
// speedup vs baseline: 1.0465x; 1.0465x over previous
#include <cuda_runtime.h>
#include <cstdint>

#define WPB 4                 // warps per block
#define SERIAL 2              // serial graph-quads per warp (8 graphs/warp total)
#define GSTRIDE 836           // floats per graph region; == 4 mod 32 (bank-disjoint quads)
#define NREG (WPB * 4)        // 16 concurrent graph regions per block
#define SMEM_FLOATS (NREG * GSTRIDE + 16)
#define SMEM_BYTES (SMEM_FLOATS * 4)

// region-internal offsets (floats)
#define OFF_NA 512            // 16x16 nA (rows, chunk-rotated)
#define OFF_DS 768
#define OFF_XS 784
#define OFF_YS 800
#define OFF_TS 816
#define ASTR 20               // raw-z staging row stride (floats); strip = 16x20, aliases HT

__device__ float g_Wt[2048];  // [layer][k][h] transposed weights

__global__ void wt_kernel(const float* __restrict__ w2, const float* __restrict__ w3) {
    for (int idx = threadIdx.x; idx < 2048; idx += blockDim.x) {
        int m = idx >> 10, rem = idx & 1023, k = rem >> 5, h = rem & 31;
        g_Wt[idx] = (m ? w3 : w2)[h * 32 + k];
    }
}

// ---------- packed f32x2 helpers (Blackwell fma.rn.f32x2, PTX-only) ----------
__device__ __forceinline__ unsigned long long fma2(unsigned long long a,
                                                   unsigned long long b,
                                                   unsigned long long c) {
    unsigned long long d;
    asm("fma.rn.f32x2 %0, %1, %2, %3;" : "=l"(d) : "l"(a), "l"(b), "l"(c));
    return d;
}
__device__ __forceinline__ unsigned long long pack2(float lo, float hi) {
    unsigned long long r;
    asm("mov.b64 %0, {%1, %2};" : "=l"(r) : "f"(lo), "f"(hi));
    return r;
}
__device__ __forceinline__ unsigned long long dup2(float v) {
    unsigned long long r;
    asm("mov.b64 %0, {%1, %1};" : "=l"(r) : "f"(v));
    return r;
}
__device__ __forceinline__ float hsum2(unsigned long long v) {
    float a, b;
    asm("mov.b64 {%0, %1}, %2;" : "=f"(a), "=f"(b) : "l"(v));
    return a + b;
}
__device__ __forceinline__ void unpack2(unsigned long long v, float& a, float& b) {
    asm("mov.b64 {%0, %1}, %2;" : "=f"(a), "=f"(b) : "l"(v));
}
__device__ __forceinline__ uint32_t smem_u32(const void* p) {
    uint32_t a;
    asm("{ .reg .u64 t; cvta.to.shared.u64 t, %1; cvt.u32.u64 %0, t; }" : "=r"(a) : "l"(p));
    return a;
}
__device__ __forceinline__ void cp_async16(uint32_t dst, const void* src) {
    asm volatile("cp.async.ca.shared.global [%0], [%1], 16;" :: "r"(dst), "l"(src));
}
#define CP_COMMIT() asm volatile("cp.async.commit_group;" ::: "memory")
#define CP_WAIT0()  asm volatile("cp.async.wait_group 0;" ::: "memory")

// stage raw z rows r0,r1 of this lane's graph into the RAW strip (16B chunks)
__device__ __forceinline__ void stage_z(uint32_t raw_s, const float* zg, int r0) {
#pragma unroll
    for (int rr = 0; rr < 2; rr++) {
        const int r = r0 + rr;
#pragma unroll
        for (int q = 0; q < 4; q++)
            cp_async16(raw_s + (uint32_t)(r * (ASTR * 4) + q * 16),
                       zg + r * 16 + 4 * q);
    }
}

// G[j][h_c] += sum_k H[j][k] * W[h_c][k]  (j-pair packed; HT k-major, slot-rotated)
__device__ __forceinline__ void hw_layer_q(const float* __restrict__ HT,
                                           const float* __restrict__ wt,     // g_Wt + m*1024
                                           const float* __restrict__ bias,   // layer bias
                                           int j0,
                                           unsigned long long Gp[4][8]) {
    float4 bv = *(const float4*)(bias + 4 * j0);
    unsigned long long b0 = dup2(bv.x), b1 = dup2(bv.y), b2 = dup2(bv.z), b3 = dup2(bv.w);
#pragma unroll
    for (int jp = 0; jp < 8; jp++) {
        Gp[0][jp] = b0; Gp[1][jp] = b1; Gp[2][jp] = b2; Gp[3][jp] = b3;
    }
#pragma unroll
    for (int k = 0; k < 32; k++) {
        const int rot = k >> 2;                       // slot rotation used by row-k's writer
        const ulonglong2* row = (const ulonglong2*)(HT + k * 16);
        ulonglong2 c0 = row[0], c1 = row[1], c2 = row[2], c3 = row[3];
        unsigned long long u[8] = {c0.x, c0.y, c1.x, c1.y, c2.x, c2.y, c3.x, c3.y};
        float4 wv = *(const float4*)(wt + k * 32 + 4 * j0);
        unsigned long long w0 = dup2(wv.x), w1 = dup2(wv.y), w2 = dup2(wv.z), w3 = dup2(wv.w);
#pragma unroll
        for (int jp = 0; jp < 8; jp++) {
            unsigned long long hv = u[(jp + rot) & 7];
            Gp[0][jp] = fma2(hv, w0, Gp[0][jp]);
            Gp[1][jp] = fma2(hv, w1, Gp[1][jp]);
            Gp[2][jp] = fma2(hv, w2, Gp[2][jp]);
            Gp[3][jp] = fma2(hv, w3, Gp[3][jp]);
        }
    }
}

// H[i][h_c] = relu(nA_row_i . G[.][h_c]); STORE -> HT (rotated), else pool into e[]
template <bool STORE>
__device__ __forceinline__ void propagate_q(const float* __restrict__ NAp,
                                            float* __restrict__ HT,
                                            const unsigned long long Gp[4][8],
                                            int j0, float* e) {
#pragma unroll
    for (int t = 0; t < 8; t++) {
        float h[2][4];
#pragma unroll
        for (int ii = 0; ii < 2; ii++) {
            const int i = 2 * t + ii;
            const int rc = (i >> 1) & 3;              // NA row chunk rotation
            unsigned long long a0 = 0ULL, a1 = 0ULL, a2 = 0ULL, a3 = 0ULL;
#pragma unroll
            for (int p = 0; p < 4; p++) {
                const int q = (p - rc) & 3;           // logical chunk at physical p
                ulonglong2 nn = *(const ulonglong2*)(NAp + i * 16 + 4 * p);
                a0 = fma2(nn.x, Gp[0][2 * q], a0); a0 = fma2(nn.y, Gp[0][2 * q + 1], a0);
                a1 = fma2(nn.x, Gp[1][2 * q], a1); a1 = fma2(nn.y, Gp[1][2 * q + 1], a1);
                a2 = fma2(nn.x, Gp[2][2 * q], a2); a2 = fma2(nn.y, Gp[2][2 * q + 1], a2);
                a3 = fma2(nn.x, Gp[3][2 * q], a3); a3 = fma2(nn.y, Gp[3][2 * q + 1], a3);
            }
            h[ii][0] = fmaxf(hsum2(a0), 0.0f);
            h[ii][1] = fmaxf(hsum2(a1), 0.0f);
            h[ii][2] = fmaxf(hsum2(a2), 0.0f);
            h[ii][3] = fmaxf(hsum2(a3), 0.0f);
        }
        if (STORE) {
            const int sp = (t + j0) & 7;              // rotated u64 slot
#pragma unroll
            for (int c = 0; c < 4; c++)
                *(unsigned long long*)(HT + (4 * j0 + c) * 16 + 2 * sp) = pack2(h[0][c], h[1][c]);
        } else {
            e[0] += h[0][0] + h[1][0];
            e[1] += h[0][1] + h[1][1];
            e[2] += h[0][2] + h[1][2];
            e[3] += h[0][3] + h[1][3];
        }
    }
}

__global__ void __launch_bounds__(WPB * 32, 4)
gcn_kernel(const float* __restrict__ z,
           const float* __restrict__ node_emb,
           const float* __restrict__ spw,
           const float* __restrict__ spb,
           const float* __restrict__ alpha,
           const float* __restrict__ w1_w, const float* __restrict__ w1_b,
           const float* __restrict__ w2_b, const float* __restrict__ w3_b,
           const float* __restrict__ fc_w, const float* __restrict__ fc_b,
           float* __restrict__ out, int batch)
{
    extern __shared__ float smem[];
    float* spwsm = smem + NREG * GSTRIDE;

    const int tid = threadIdx.x;
    const int wid  = tid >> 5;
    const int l    = tid & 31;
    const int j0   = l & 7;       // lane within graph group: nodes {2j0,2j0+1}, hidden {4j0..4j0+3}
    const int gsel = l >> 3;      // which of 4 concurrent graphs

    float* GR  = smem + (wid * 4 + gsel) * GSTRIDE;
    float* HT  = GR;              // 32x16 k-major hidden (aliases 16x20 raw-z strip)
    float* RAW = GR;              // raw z staging (prep only)
    float* NAp = GR + OFF_NA;
    const uint32_t raw_s = smem_u32(RAW);

    const int r0 = 2 * j0, r1 = 2 * j0 + 1;

    long long warpbase = ((long long)blockIdx.x * WPB + wid) * (4 * SERIAL);

    // stage quad 0's z (covered by weight staging + syncthreads)
    {
        long long g0 = warpbase + gsel;
        stage_z(raw_s, z + (g0 < batch ? g0 : 0) * 256, r0);
        CP_COMMIT();
    }

    if (tid < 16) spwsm[tid] = spw[tid];
    __syncthreads();

    // persistent lane constants
    float ne0, ne1;
    { float2 nv = *(const float2*)(node_emb + r0); ne0 = nv.x; ne1 = nv.y; }
    float spw0, spw1;
    { float2 wv = *(const float2*)(spwsm + r0); spw0 = wv.x; spw1 = wv.y; }
    const float spb0 = spb[0];
    const float blend = 1.0f / (1.0f + expf(-alpha[0]));
    const float omb = 1.0f - blend;
    float SW = 0.0f;              // sum of spw (for affine struct projection)
#pragma unroll
    for (int q = 0; q < 4; q++) {
        float4 w = *(const float4*)(spwsm + 4 * q);
        SW += w.x + w.y + w.z + w.w;
    }

#pragma unroll 1
    for (int si = 0; si < SERIAL; si++) {
        long long g = warpbase + si * 4 + gsel;
        const bool valid = (g < batch);

        // wait for this quad's staged z
        CP_WAIT0();
        __syncwarp();

        // ---- symmetrize + fused local sums (independent of the shfl tree) ----
        float s0[16], s1[16];
        float mn = 1e30f, mx = -1e30f;
        float ss0 = 0.0f, ss1 = 0.0f, sw0 = 0.0f, sw1 = 0.0f;
#pragma unroll
        for (int q = 0; q < 4; q++) {
            float4 v0 = *(const float4*)(RAW + r0 * ASTR + 4 * q);
            float4 v1 = *(const float4*)(RAW + r1 * ASTR + 4 * q);
            float4 w  = *(const float4*)(spwsm + 4 * q);
#pragma unroll
            for (int t = 0; t < 4; t++) {
                const int i = 4 * q + t;
                float2 c = *(const float2*)(RAW + i * ASTR + r0);  // z[i][r0], z[i][r1]
                float rv0 = (t == 0) ? v0.x : (t == 1) ? v0.y : (t == 2) ? v0.z : v0.w;
                float rv1 = (t == 0) ? v1.x : (t == 1) ? v1.y : (t == 2) ? v1.z : v1.w;
                float wt  = (t == 0) ? w.x  : (t == 1) ? w.y  : (t == 2) ? w.z  : w.w;
                float sv0 = 0.5f * (fabsf(rv0) + fabsf(c.x));
                float sv1 = 0.5f * (fabsf(rv1) + fabsf(c.y));
                s0[i] = sv0; s1[i] = sv1;
                mn = fminf(mn, fminf(sv0, sv1));
                mx = fmaxf(mx, fmaxf(sv0, sv1));
                ss0 += sv0; ss1 += sv1;
                sw0 += sv0 * wt; sw1 += sv1 * wt;
            }
        }
#pragma unroll
        for (int m = 4; m >= 1; m >>= 1) {
            mn = fminf(mn, __shfl_xor_sync(0xffffffffu, mn, m));
            mx = fmaxf(mx, __shfl_xor_sync(0xffffffffu, mx, m));
        }
        const float inv = 1.0f / (mx - mn + 1e-6f);

        // ---- affine row sums / struct projection (no normalize loop) ----
        // A_hat contains the identity: its diagonal contributes +1 to the row
        // sum and +spw[row] to the struct projection.
        const float rs0 = inv * (ss0 - 16.0f * mn) + 1.0f;
        const float rs1 = inv * (ss1 - 16.0f * mn) + 1.0f;
        const float sx0 = inv * (sw0 - mn * SW) + spw0;
        const float sx1 = inv * (sw1 - mn * SW) + spw1;
        const float d0 = rsqrtf(rs0 + 1e-6f);
        const float d1 = rsqrtf(rs1 + 1e-6f);
        const float x0 = blend * (sx0 + spb0) + omb * ne0;
        const float x1 = blend * (sx1 + spb0) + omb * ne1;
        *(unsigned long long*)(GR + OFF_DS + r0) = pack2(d0, d1);
        *(unsigned long long*)(GR + OFF_XS + r0) = pack2(x0, x1);
        __syncwarp();

        // ---- nA rows r0,r1 (normalization folded in); fold t = nA@1, y = nA@X ----
        float t0 = 0.0f, t1 = 0.0f, y0 = 0.0f, y1 = 0.0f;
        const float c0f = d0 * inv, c1f = d1 * inv;
        const float d00 = d0 * d0, d11 = d1 * d1;
#pragma unroll
        for (int q = 0; q < 4; q++) {
            float4 dd = *(const float4*)(GR + OFF_DS + 4 * q);
            float4 xv = *(const float4*)(GR + OFF_XS + 4 * q);
            float na0[4], na1[4];
#pragma unroll
            for (int t = 0; t < 4; t++) {
                const int i = 4 * q + t;
                float ddt = (t == 0) ? dd.x : (t == 1) ? dd.y : (t == 2) ? dd.z : dd.w;
                na0[t] = (c0f * ddt) * (s0[i] - mn);
                na1[t] = (c1f * ddt) * (s1[i] - mn);
                if (i == r0) na0[t] += d00;            // diagonal (+eye) term
                if (i == r1) na1[t] += d11;
            }
            t0 += na0[0] + na0[1] + na0[2] + na0[3];
            t1 += na1[0] + na1[1] + na1[2] + na1[3];
            y0 += na0[0] * xv.x + na0[1] * xv.y + na0[2] * xv.z + na0[3] * xv.w;
            y1 += na1[0] * xv.x + na1[1] * xv.y + na1[2] * xv.z + na1[3] * xv.w;
            const int p = (q + j0) & 3;               // rotated chunk position
            *(float4*)(NAp + r0 * 16 + 4 * p) = make_float4(na0[0], na0[1], na0[2], na0[3]);
            *(float4*)(NAp + r1 * 16 + 4 * p) = make_float4(na1[0], na1[1], na1[2], na1[3]);
        }
        *(unsigned long long*)(GR + OFF_YS + r0) = pack2(y0, y1);
        *(unsigned long long*)(GR + OFF_TS + r0) = pack2(t0, t1);
        __syncwarp();

        // ---- layer 1 (rank-2): H1[i][h] = relu(y_i*w1_h + t_i*b1_h) -> HT ----
        // (overwrites RAW strip; raw reads all completed before the prior syncwarp)
        {
            float4 w1v = *(const float4*)(w1_w + 4 * j0);
            float4 b1v = *(const float4*)(w1_b + 4 * j0);
#pragma unroll
            for (int t = 0; t < 8; t++) {
                float ya, yb, ta, tb;
                unpack2(*(const unsigned long long*)(GR + OFF_YS + 2 * t), ya, yb);
                unpack2(*(const unsigned long long*)(GR + OFF_TS + 2 * t), ta, tb);
                float ha[4], hb[4];
                ha[0] = fmaxf(ya * w1v.x + ta * b1v.x, 0.0f);
                ha[1] = fmaxf(ya * w1v.y + ta * b1v.y, 0.0f);
                ha[2] = fmaxf(ya * w1v.z + ta * b1v.z, 0.0f);
                ha[3] = fmaxf(ya * w1v.w + ta * b1v.w, 0.0f);
                hb[0] = fmaxf(yb * w1v.x + tb * b1v.x, 0.0f);
                hb[1] = fmaxf(yb * w1v.y + tb * b1v.y, 0.0f);
                hb[2] = fmaxf(yb * w1v.z + tb * b1v.z, 0.0f);
                hb[3] = fmaxf(yb * w1v.w + tb * b1v.w, 0.0f);
                const int sp = (t + j0) & 7;
#pragma unroll
                for (int c = 0; c < 4; c++)
                    *(unsigned long long*)(HT + (4 * j0 + c) * 16 + 2 * sp) = pack2(ha[c], hb[c]);
            }
        }
        __syncwarp();

        unsigned long long Gp[4][8];
        hw_layer_q(HT, g_Wt, w2_b, j0, Gp);           // G2 = H1@W2^T + b2
        __syncwarp();                                 // HT reads done before overwrite
        propagate_q<true>(NAp, HT, Gp, j0, nullptr);  // H2 -> HT
        __syncwarp();

        hw_layer_q(HT, g_Wt + 1024, w3_b, j0, Gp);    // G3 = H2@W3^T + b3
        __syncwarp();

        // HT is dead from here on: stage next quad's z into the strip (async,
        // hides DRAM latency under propagate_pool + logits)
        if (si + 1 < SERIAL) {
            long long gn = warpbase + (si + 1) * 4 + gsel;
            stage_z(raw_s, z + (gn < batch ? gn : 0) * 256, r0);
            CP_COMMIT();
        }

        float e[4] = {0.0f, 0.0f, 0.0f, 0.0f};
        propagate_q<false>(NAp, HT, Gp, j0, e);       // H3 column sums (pool)

        // ---- logits ----
        float4 f0 = *(const float4*)(fc_w + 4 * j0);
        float4 f1 = *(const float4*)(fc_w + 32 + 4 * j0);
        float p0 = e[0] * f0.x + e[1] * f0.y + e[2] * f0.z + e[3] * f0.w;
        float p1 = e[0] * f1.x + e[1] * f1.y + e[2] * f1.z + e[3] * f1.w;
#pragma unroll
        for (int m = 4; m >= 1; m >>= 1) {
            p0 += __shfl_xor_sync(0xffffffffu, p0, m);
            p1 += __shfl_xor_sync(0xffffffffu, p1, m);
        }
        if (j0 == 0 && valid) {
            float2 o;
            o.x = p0 * 0.0625f + fc_b[0];
            o.y = p1 * 0.0625f + fc_b[1];
            *(float2*)(out + g * 2) = o;
        }
        __syncwarp();
    }
}

extern "C" void kernel_launch(void* const* d_in, const int* in_sizes, int n_in,
                              void* d_out, int out_size)
{
    const float* z     = (const float*)d_in[0];
    const float* nemb  = (const float*)d_in[1];
    const float* spw   = (const float*)d_in[2];
    const float* spb   = (const float*)d_in[3];
    const float* alpha = (const float*)d_in[4];
    const float* w1w   = (const float*)d_in[5];
    const float* w1b   = (const float*)d_in[6];
    const float* w2w   = (const float*)d_in[7];
    const float* w2b   = (const float*)d_in[8];
    const float* w3w   = (const float*)d_in[9];
    const float* w3b   = (const float*)d_in[10];
    const float* fcw   = (const float*)d_in[11];
    const float* fcb   = (const float*)d_in[12];
    float* out = (float*)d_out;

    int batch = in_sizes[0] / 256;
    int graphs_per_block = WPB * 4 * SERIAL;
    int blocks = (batch + graphs_per_block - 1) / graphs_per_block;

    static bool attr_set = false;
    if (!attr_set) {
        cudaFuncSetAttribute(gcn_kernel, cudaFuncAttributeMaxDynamicSharedMemorySize,
                             SMEM_BYTES);
        attr_set = true;
    }

    wt_kernel<<<1, 256>>>(w2w, w3w);
    gcn_kernel<<<blocks, WPB * 32, SMEM_BYTES>>>(
        z, nemb, spw, spb, alpha, w1w, w1b, w2b, w3b, fcw, fcb, out, batch);
}

// round 15
// speedup vs baseline: 1.0531x; 1.0063x over previous
#include <cuda_runtime.h>
#include <cstdint>

#define WPB 4                 // warps per block
#define SERIAL 2              // serial graph-quads per warp (8 graphs/warp total)
#define GSTRIDE 840           // floats per graph region; == 8 mod 32 (2-way max cross-region)
#define NREG (WPB * 4)        // 16 concurrent graph regions per block
#define SMEM_FLOATS (NREG * GSTRIDE + 16)
#define SMEM_BYTES (SMEM_FLOATS * 4)

// region-internal offsets (floats)
#define OFF_NA 512            // 16x16 nA (rows, chunk-rotated)
#define OFF_DS 768
#define OFF_XS 784
#define OFF_YS 800
#define OFF_TS 816
#define ASTR 20               // raw-z staging row stride (floats); strip = 16x20, aliases HT

__device__ float g_Wt[2048];  // [layer][k][h] transposed weights

__global__ void wt_kernel(const float* __restrict__ w2, const float* __restrict__ w3) {
    for (int idx = threadIdx.x; idx < 2048; idx += blockDim.x) {
        int m = idx >> 10, rem = idx & 1023, k = rem >> 5, h = rem & 31;
        g_Wt[idx] = (m ? w3 : w2)[h * 32 + k];
    }
}

// ---------- packed f32x2 helpers (Blackwell fma.rn.f32x2, PTX-only) ----------
__device__ __forceinline__ unsigned long long fma2(unsigned long long a,
                                                   unsigned long long b,
                                                   unsigned long long c) {
    unsigned long long d;
    asm("fma.rn.f32x2 %0, %1, %2, %3;" : "=l"(d) : "l"(a), "l"(b), "l"(c));
    return d;
}
__device__ __forceinline__ unsigned long long pack2(float lo, float hi) {
    unsigned long long r;
    asm("mov.b64 %0, {%1, %2};" : "=l"(r) : "f"(lo), "f"(hi));
    return r;
}
__device__ __forceinline__ unsigned long long dup2(float v) {
    unsigned long long r;
    asm("mov.b64 %0, {%1, %1};" : "=l"(r) : "f"(v));
    return r;
}
__device__ __forceinline__ float hsum2(unsigned long long v) {
    float a, b;
    asm("mov.b64 {%0, %1}, %2;" : "=f"(a), "=f"(b) : "l"(v));
    return a + b;
}
__device__ __forceinline__ void unpack2(unsigned long long v, float& a, float& b) {
    asm("mov.b64 {%0, %1}, %2;" : "=f"(a), "=f"(b) : "l"(v));
}
__device__ __forceinline__ uint32_t smem_u32(const void* p) {
    uint32_t a;
    asm("{ .reg .u64 t; cvta.to.shared.u64 t, %1; cvt.u32.u64 %0, t; }" : "=r"(a) : "l"(p));
    return a;
}
__device__ __forceinline__ void cp_async16(uint32_t dst, const void* src) {
    asm volatile("cp.async.ca.shared.global [%0], [%1], 16;" :: "r"(dst), "l"(src));
}
#define CP_COMMIT() asm volatile("cp.async.commit_group;" ::: "memory")
#define CP_WAIT0()  asm volatile("cp.async.wait_group 0;" ::: "memory")

// stage raw z rows r0,r1 of this lane's graph into the RAW strip (16B chunks)
__device__ __forceinline__ void stage_z(uint32_t raw_s, const float* zg, int r0) {
#pragma unroll
    for (int rr = 0; rr < 2; rr++) {
        const int r = r0 + rr;
#pragma unroll
        for (int q = 0; q < 4; q++)
            cp_async16(raw_s + (uint32_t)(r * (ASTR * 4) + q * 16),
                       zg + r * 16 + 4 * q);
    }
}

// G[j][h_c] += sum_k H[j][k] * W[h_c][k]  (j-pair packed; HT k-major, slot-rotated)
__device__ __forceinline__ void hw_layer_q(const float* __restrict__ HT,
                                           const float* __restrict__ wt,     // g_Wt + m*1024
                                           const float* __restrict__ bias,   // layer bias
                                           int j0,
                                           unsigned long long Gp[4][8]) {
    float4 bv = *(const float4*)(bias + 4 * j0);
    unsigned long long b0 = dup2(bv.x), b1 = dup2(bv.y), b2 = dup2(bv.z), b3 = dup2(bv.w);
#pragma unroll
    for (int jp = 0; jp < 8; jp++) {
        Gp[0][jp] = b0; Gp[1][jp] = b1; Gp[2][jp] = b2; Gp[3][jp] = b3;
    }
#pragma unroll
    for (int k = 0; k < 32; k++) {
        const int rot = k >> 2;                       // slot rotation used by row-k's writer
        const ulonglong2* row = (const ulonglong2*)(HT + k * 16);
        ulonglong2 c0 = row[0], c1 = row[1], c2 = row[2], c3 = row[3];
        unsigned long long u[8] = {c0.x, c0.y, c1.x, c1.y, c2.x, c2.y, c3.x, c3.y};
        float4 wv = *(const float4*)(wt + k * 32 + 4 * j0);
        unsigned long long w0 = dup2(wv.x), w1 = dup2(wv.y), w2 = dup2(wv.z), w3 = dup2(wv.w);
#pragma unroll
        for (int jp = 0; jp < 8; jp++) {
            unsigned long long hv = u[(jp + rot) & 7];
            Gp[0][jp] = fma2(hv, w0, Gp[0][jp]);
            Gp[1][jp] = fma2(hv, w1, Gp[1][jp]);
            Gp[2][jp] = fma2(hv, w2, Gp[2][jp]);
            Gp[3][jp] = fma2(hv, w3, Gp[3][jp]);
        }
    }
}

// H[i][h_c] = relu(nA_row_i . G[.][h_c]); STORE -> HT (rotated), else pool into e[]
template <bool STORE>
__device__ __forceinline__ void propagate_q(const float* __restrict__ NAp,
                                            float* __restrict__ HT,
                                            const unsigned long long Gp[4][8],
                                            int j0, float* e) {
#pragma unroll
    for (int t = 0; t < 8; t++) {
        float h[2][4];
#pragma unroll
        for (int ii = 0; ii < 2; ii++) {
            const int i = 2 * t + ii;
            const int rc = (i >> 1) & 3;              // NA row chunk rotation
            unsigned long long a0 = 0ULL, a1 = 0ULL, a2 = 0ULL, a3 = 0ULL;
#pragma unroll
            for (int p = 0; p < 4; p++) {
                const int q = (p - rc) & 3;           // logical chunk at physical p
                ulonglong2 nn = *(const ulonglong2*)(NAp + i * 16 + 4 * p);
                a0 = fma2(nn.x, Gp[0][2 * q], a0); a0 = fma2(nn.y, Gp[0][2 * q + 1], a0);
                a1 = fma2(nn.x, Gp[1][2 * q], a1); a1 = fma2(nn.y, Gp[1][2 * q + 1], a1);
                a2 = fma2(nn.x, Gp[2][2 * q], a2); a2 = fma2(nn.y, Gp[2][2 * q + 1], a2);
                a3 = fma2(nn.x, Gp[3][2 * q], a3); a3 = fma2(nn.y, Gp[3][2 * q + 1], a3);
            }
            h[ii][0] = fmaxf(hsum2(a0), 0.0f);
            h[ii][1] = fmaxf(hsum2(a1), 0.0f);
            h[ii][2] = fmaxf(hsum2(a2), 0.0f);
            h[ii][3] = fmaxf(hsum2(a3), 0.0f);
        }
        if (STORE) {
            const int sp = (t + j0) & 7;              // rotated u64 slot
#pragma unroll
            for (int c = 0; c < 4; c++)
                *(unsigned long long*)(HT + (4 * j0 + c) * 16 + 2 * sp) = pack2(h[0][c], h[1][c]);
        } else {
            e[0] += h[0][0] + h[1][0];
            e[1] += h[0][1] + h[1][1];
            e[2] += h[0][2] + h[1][2];
            e[3] += h[0][3] + h[1][3];
        }
    }
}

__global__ void __launch_bounds__(WPB * 32, 4)
gcn_kernel(const float* __restrict__ z,
           const float* __restrict__ node_emb,
           const float* __restrict__ spw,
           const float* __restrict__ spb,
           const float* __restrict__ alpha,
           const float* __restrict__ w1_w, const float* __restrict__ w1_b,
           const float* __restrict__ w2_b, const float* __restrict__ w3_b,
           const float* __restrict__ fc_w, const float* __restrict__ fc_b,
           float* __restrict__ out, int batch)
{
    extern __shared__ float smem[];
    float* spwsm = smem + NREG * GSTRIDE;

    const int tid = threadIdx.x;
    const int wid  = tid >> 5;
    const int l    = tid & 31;
    const int j0   = l & 7;       // lane within graph group: nodes {2j0,2j0+1}, hidden {4j0..4j0+3}
    const int gsel = l >> 3;      // which of 4 concurrent graphs

    float* GR  = smem + (wid * 4 + gsel) * GSTRIDE;
    float* HT  = GR;              // 32x16 k-major hidden (aliases 16x20 raw-z strip)
    float* RAW = GR;              // raw z staging (prep only)
    float* NAp = GR + OFF_NA;
    const uint32_t raw_s = smem_u32(RAW);

    const int r0 = 2 * j0, r1 = 2 * j0 + 1;

    long long warpbase = ((long long)blockIdx.x * WPB + wid) * (4 * SERIAL);

    // stage quad 0's z (covered by weight staging + syncthreads)
    {
        long long g0 = warpbase + gsel;
        stage_z(raw_s, z + (g0 < batch ? g0 : 0) * 256, r0);
        CP_COMMIT();
    }

    if (tid < 16) spwsm[tid] = spw[tid];
    __syncthreads();

    // persistent lane constants
    float ne0, ne1;
    { float2 nv = *(const float2*)(node_emb + r0); ne0 = nv.x; ne1 = nv.y; }
    float spw0, spw1;
    { float2 wv = *(const float2*)(spwsm + r0); spw0 = wv.x; spw1 = wv.y; }
    const float spb0 = spb[0];
    const float blend = 1.0f / (1.0f + expf(-alpha[0]));
    const float omb = 1.0f - blend;
    float SW = 0.0f;              // sum of spw (for affine struct projection)
#pragma unroll
    for (int q = 0; q < 4; q++) {
        float4 w = *(const float4*)(spwsm + 4 * q);
        SW += w.x + w.y + w.z + w.w;
    }

#pragma unroll 1
    for (int si = 0; si < SERIAL; si++) {
        long long g = warpbase + si * 4 + gsel;
        const bool valid = (g < batch);

        // wait for this quad's staged z
        CP_WAIT0();
        __syncwarp();

        // ---- symmetrize + fused local sums (independent of the shfl tree) ----
        float s0[16], s1[16];
        float mn = 1e30f, mx = -1e30f;
        float ss0 = 0.0f, ss1 = 0.0f, sw0 = 0.0f, sw1 = 0.0f;
#pragma unroll
        for (int q = 0; q < 4; q++) {
            float4 v0 = *(const float4*)(RAW + r0 * ASTR + 4 * q);
            float4 v1 = *(const float4*)(RAW + r1 * ASTR + 4 * q);
            float4 w  = *(const float4*)(spwsm + 4 * q);
#pragma unroll
            for (int t = 0; t < 4; t++) {
                const int i = 4 * q + t;
                float2 c = *(const float2*)(RAW + i * ASTR + r0);  // z[i][r0], z[i][r1]
                float rv0 = (t == 0) ? v0.x : (t == 1) ? v0.y : (t == 2) ? v0.z : v0.w;
                float rv1 = (t == 0) ? v1.x : (t == 1) ? v1.y : (t == 2) ? v1.z : v1.w;
                float wt  = (t == 0) ? w.x  : (t == 1) ? w.y  : (t == 2) ? w.z  : w.w;
                float sv0 = 0.5f * (fabsf(rv0) + fabsf(c.x));
                float sv1 = 0.5f * (fabsf(rv1) + fabsf(c.y));
                s0[i] = sv0; s1[i] = sv1;
                mn = fminf(mn, fminf(sv0, sv1));
                mx = fmaxf(mx, fmaxf(sv0, sv1));
                ss0 += sv0; ss1 += sv1;
                sw0 += sv0 * wt; sw1 += sv1 * wt;
            }
        }
#pragma unroll
        for (int m = 4; m >= 1; m >>= 1) {
            mn = fminf(mn, __shfl_xor_sync(0xffffffffu, mn, m));
            mx = fmaxf(mx, __shfl_xor_sync(0xffffffffu, mx, m));
        }
        const float inv = 1.0f / (mx - mn + 1e-6f);

        // ---- affine row sums / struct projection (no normalize loop) ----
        // A_hat contains the identity: its diagonal contributes +1 to the row
        // sum and +spw[row] to the struct projection.
        const float rs0 = inv * (ss0 - 16.0f * mn) + 1.0f;
        const float rs1 = inv * (ss1 - 16.0f * mn) + 1.0f;
        const float sx0 = inv * (sw0 - mn * SW) + spw0;
        const float sx1 = inv * (sw1 - mn * SW) + spw1;
        const float d0 = rsqrtf(rs0 + 1e-6f);
        const float d1 = rsqrtf(rs1 + 1e-6f);
        const float x0 = blend * (sx0 + spb0) + omb * ne0;
        const float x1 = blend * (sx1 + spb0) + omb * ne1;
        *(unsigned long long*)(GR + OFF_DS + r0) = pack2(d0, d1);
        *(unsigned long long*)(GR + OFF_XS + r0) = pack2(x0, x1);
        __syncwarp();

        // ---- nA rows r0,r1 (normalization folded in); fold t = nA@1, y = nA@X ----
        float t0 = 0.0f, t1 = 0.0f, y0 = 0.0f, y1 = 0.0f;
        const float c0f = d0 * inv, c1f = d1 * inv;
        const float d00 = d0 * d0, d11 = d1 * d1;
#pragma unroll
        for (int q = 0; q < 4; q++) {
            float4 dd = *(const float4*)(GR + OFF_DS + 4 * q);
            float4 xv = *(const float4*)(GR + OFF_XS + 4 * q);
            float na0[4], na1[4];
#pragma unroll
            for (int t = 0; t < 4; t++) {
                const int i = 4 * q + t;
                float ddt = (t == 0) ? dd.x : (t == 1) ? dd.y : (t == 2) ? dd.z : dd.w;
                na0[t] = (c0f * ddt) * (s0[i] - mn);
                na1[t] = (c1f * ddt) * (s1[i] - mn);
                if (i == r0) na0[t] += d00;            // diagonal (+eye) term
                if (i == r1) na1[t] += d11;
            }
            t0 += na0[0] + na0[1] + na0[2] + na0[3];
            t1 += na1[0] + na1[1] + na1[2] + na1[3];
            y0 += na0[0] * xv.x + na0[1] * xv.y + na0[2] * xv.z + na0[3] * xv.w;
            y1 += na1[0] * xv.x + na1[1] * xv.y + na1[2] * xv.z + na1[3] * xv.w;
            const int p = (q + j0) & 3;               // rotated chunk position
            *(float4*)(NAp + r0 * 16 + 4 * p) = make_float4(na0[0], na0[1], na0[2], na0[3]);
            *(float4*)(NAp + r1 * 16 + 4 * p) = make_float4(na1[0], na1[1], na1[2], na1[3]);
        }
        *(unsigned long long*)(GR + OFF_YS + r0) = pack2(y0, y1);
        *(unsigned long long*)(GR + OFF_TS + r0) = pack2(t0, t1);
        __syncwarp();

        // ---- layer 1 (rank-2): H1[i][h] = relu(y_i*w1_h + t_i*b1_h) -> HT ----
        // (overwrites RAW strip; raw reads all completed before the prior syncwarp)
        {
            float4 w1v = *(const float4*)(w1_w + 4 * j0);
            float4 b1v = *(const float4*)(w1_b + 4 * j0);
#pragma unroll
            for (int t = 0; t < 8; t++) {
                float ya, yb, ta, tb;
                unpack2(*(const unsigned long long*)(GR + OFF_YS + 2 * t), ya, yb);
                unpack2(*(const unsigned long long*)(GR + OFF_TS + 2 * t), ta, tb);
                float ha[4], hb[4];
                ha[0] = fmaxf(ya * w1v.x + ta * b1v.x, 0.0f);
                ha[1] = fmaxf(ya * w1v.y + ta * b1v.y, 0.0f);
                ha[2] = fmaxf(ya * w1v.z + ta * b1v.z, 0.0f);
                ha[3] = fmaxf(ya * w1v.w + ta * b1v.w, 0.0f);
                hb[0] = fmaxf(yb * w1v.x + tb * b1v.x, 0.0f);
                hb[1] = fmaxf(yb * w1v.y + tb * b1v.y, 0.0f);
                hb[2] = fmaxf(yb * w1v.z + tb * b1v.z, 0.0f);
                hb[3] = fmaxf(yb * w1v.w + tb * b1v.w, 0.0f);
                const int sp = (t + j0) & 7;
#pragma unroll
                for (int c = 0; c < 4; c++)
                    *(unsigned long long*)(HT + (4 * j0 + c) * 16 + 2 * sp) = pack2(ha[c], hb[c]);
            }
        }
        __syncwarp();

        unsigned long long Gp[4][8];
        hw_layer_q(HT, g_Wt, w2_b, j0, Gp);           // G2 = H1@W2^T + b2
        __syncwarp();                                 // HT reads done before overwrite
        propagate_q<true>(NAp, HT, Gp, j0, nullptr);  // H2 -> HT
        __syncwarp();

        hw_layer_q(HT, g_Wt + 1024, w3_b, j0, Gp);    // G3 = H2@W3^T + b3
        __syncwarp();

        // HT is dead from here on: stage next quad's z into the strip (async,
        // hides DRAM latency under propagate_pool + logits)
        if (si + 1 < SERIAL) {
            long long gn = warpbase + (si + 1) * 4 + gsel;
            stage_z(raw_s, z + (gn < batch ? gn : 0) * 256, r0);
            CP_COMMIT();
        }

        float e[4] = {0.0f, 0.0f, 0.0f, 0.0f};
        propagate_q<false>(NAp, HT, Gp, j0, e);       // H3 column sums (pool)

        // ---- logits ----
        float4 f0 = *(const float4*)(fc_w + 4 * j0);
        float4 f1 = *(const float4*)(fc_w + 32 + 4 * j0);
        float p0 = e[0] * f0.x + e[1] * f0.y + e[2] * f0.z + e[3] * f0.w;
        float p1 = e[0] * f1.x + e[1] * f1.y + e[2] * f1.z + e[3] * f1.w;
#pragma unroll
        for (int m = 4; m >= 1; m >>= 1) {
            p0 += __shfl_xor_sync(0xffffffffu, p0, m);
            p1 += __shfl_xor_sync(0xffffffffu, p1, m);
        }
        if (j0 == 0 && valid) {
            float2 o;
            o.x = p0 * 0.0625f + fc_b[0];
            o.y = p1 * 0.0625f + fc_b[1];
            *(float2*)(out + g * 2) = o;
        }
        __syncwarp();
    }
}

extern "C" void kernel_launch(void* const* d_in, const int* in_sizes, int n_in,
                              void* d_out, int out_size)
{
    const float* z     = (const float*)d_in[0];
    const float* nemb  = (const float*)d_in[1];
    const float* spw   = (const float*)d_in[2];
    const float* spb   = (const float*)d_in[3];
    const float* alpha = (const float*)d_in[4];
    const float* w1w   = (const float*)d_in[5];
    const float* w1b   = (const float*)d_in[6];
    const float* w2w   = (const float*)d_in[7];
    const float* w2b   = (const float*)d_in[8];
    const float* w3w   = (const float*)d_in[9];
    const float* w3b   = (const float*)d_in[10];
    const float* fcw   = (const float*)d_in[11];
    const float* fcb   = (const float*)d_in[12];
    float* out = (float*)d_out;

    int batch = in_sizes[0] / 256;
    int graphs_per_block = WPB * 4 * SERIAL;
    int blocks = (batch + graphs_per_block - 1) / graphs_per_block;

    static bool attr_set = false;
    if (!attr_set) {
        cudaFuncSetAttribute(gcn_kernel, cudaFuncAttributeMaxDynamicSharedMemorySize,
                             SMEM_BYTES);
        attr_set = true;
    }

    wt_kernel<<<1, 256>>>(w2w, w3w);
    gcn_kernel<<<blocks, WPB * 32, SMEM_BYTES>>>(
        z, nemb, spw, spb, alpha, w1w, w1b, w2b, w3b, fcw, fcb, out, batch);
}